// round 16
// baseline (speedup 1.0000x reference)
#include <cuda_runtime.h>
#include <cstdint>

// Problem shape (fixed for this dataset entry)
#define B_    2
#define N_    50000
#define C_    64
#define M_    50000
#define K_    16
#define H_    8
#define CMID_ 16

// Runtime-detected index width flag (int64 vs int32), set by detect kernel.
__device__ int g_idx_is64;

__global__ void detect_idx_kernel(const unsigned int* __restrict__ w) {
    if (threadIdx.x == 0 && blockIdx.x == 0) {
        int is64 = 1;
        #pragma unroll 1
        for (int i = 0; i < 256; i++) {
            if (w[2 * i + 1] != 0u) { is64 = 0; break; }
        }
        g_idx_is64 = is64;
    }
}

// TWO points per WARP (W broadcast amortized, proven in R15: L1-work 110->96us)
// + TWO PASSES over w halves (NEW): each pass accumulates only 4ch x 8w = 16
// f32x2 regs, halving R15's 96-reg footprint -> 7 CTAs/SM (occ 44% vs 28%).
// Pass cost: gather + guid re-read (feat is L2-resident; DRAM unchanged);
// W-LDS total identical to R15 (2 LDS.128/k/pass).
//
// Lane: pt = lane>>4, q = lane&15 owns channels [4q,4q+4) (one head, q>>1).
// Per k per pass per warp: 1 zero-dup LDG.128 (half-warp per point's 256B
// row) + 1 guid LDS + 2 LDS.128 W (2 distinct addrs, quarter-warp uniform)
// + 4 FMUL + 4 dup movs + 16 fma.rn.f32x2.
//
// smem: ONE 8KB blob/warp (32KB/CTA exactly -> 7 CTAs).
//   phase 1: [0,512) wn (2x256), [512,784) guid (2x136 padded), [784,816) idx
//   bounce:  pass 0 (w 0..7)  -> blob[1024,2048)   (staging never touched)
//            pass 1 (w 8..15) -> blob[0,1024)      (staging dead by then)
//   lower-half slots offset +4 so mixed-half flush phases stay conflict-free.
__global__ void __launch_bounds__(128, 7)
pcf_kernel(const float* __restrict__ feat,
           const void*  __restrict__ inds_raw,
           const float* __restrict__ guid,
           const float* __restrict__ wn,
           float* __restrict__ out)
{
    __shared__ __align__(16) float sblob[4][2048];   // 32KB total

    const int wid  = threadIdx.x >> 5;
    const int lane = threadIdx.x & 31;
    const int pair = blockIdx.x * 4 + wid;      // point-pair id in [0, B*M/2)
    const int pt   = lane >> 4;                 // which point of the pair
    const int q    = lane & 15;                 // channel quad [4q, 4q+4)
    const int p    = pair * 2 + pt;
    const int b    = (p >= M_) ? 1 : 0;
    const int hd   = q >> 1;                    // guidance head of those 4 ch

    float* swn  = sblob[wid];                   // 512 floats (2 pts x 256)
    float* sgd  = sblob[wid] + 512;             // 2 x 136 (padded stride)
    int*   sidx = (int*)(sblob[wid] + 784);     // 32 ints
    float* sou  = sblob[wid];                   // 2048 floats (bounce)

    // ---- per-warp staging: wn (2KB), guid (1KB), 32 indices ----
    {
        const float4* wsrc = (const float4*)(wn + (size_t)pair * 512);
        float4* wdst = (float4*)swn;
        #pragma unroll
        for (int r = 0; r < 4; r++)
            wdst[lane + r * 32] = __ldcs(wsrc + lane + r * 32);

        const float4* gsrc = (const float4*)(guid + (size_t)pair * 256);
        #pragma unroll
        for (int r = 0; r < 2; r++) {
            const int g   = lane + r * 32;      // 0..63 (32 float4 per point)
            const int gpt = g >> 5;
            const int off = g & 31;
            *(float4*)(sgd + gpt * 136 + off * 4) = __ldcs(gsrc + g);
        }
        long long idx;
        const size_t ioff = (size_t)pair * 32 + lane;
        if (g_idx_is64) idx = ((const long long*)inds_raw)[ioff];
        else            idx = (long long)((const int*)inds_raw)[ioff];
        sidx[lane] = (int)idx;
    }
    __syncwarp();

    const float* fb    = feat + (size_t)b * ((size_t)N_ * C_) + 4 * q;
    const float* mysgd = sgd + pt * 136;
    const float* mywn  = swn + pt * 256;
    const int*   myidx = sidx + pt * K_;

    #pragma unroll
    for (int wp = 0; wp < 2; wp++) {
        unsigned long long acc[16];
        #pragma unroll
        for (int i = 0; i < 16; i++) acc[i] = 0ull;

        // depth-1 double buffer on the gather
        ulonglong2 A = *(const ulonglong2*)(fb + (size_t)myidx[0] * C_);

        #pragma unroll 4
        for (int k = 0; k < K_; k++) {
            const ulonglong2 cur = A;
            if (k + 1 < K_)
                A = *(const ulonglong2*)(fb + (size_t)myidx[k + 1] * C_);

            const float g = mysgd[k * H_ + hd];
            const float2 f01 = *(const float2*)&cur.x;
            const float2 f23 = *(const float2*)&cur.y;
            const float m0 = f01.x * g, m1 = f01.y * g;
            const float m2 = f23.x * g, m3 = f23.y * g;
            unsigned long long d0, d1, d2, d3;
            asm("mov.b64 %0, {%1, %1};" : "=l"(d0) : "f"(m0));
            asm("mov.b64 %0, {%1, %1};" : "=l"(d1) : "f"(m1));
            asm("mov.b64 %0, {%1, %1};" : "=l"(d2) : "f"(m2));
            asm("mov.b64 %0, {%1, %1};" : "=l"(d3) : "f"(m3));

            // this pass's 8 W values (w-pairs): 2 LDS.128, 2 distinct addrs
            const ulonglong2* wr = (const ulonglong2*)(mywn + k * CMID_ + 8 * wp);
            const ulonglong2 Wa = wr[0];   // w-pairs {8wp+0,1}, {8wp+2,3}
            const ulonglong2 Wb = wr[1];   // w-pairs {8wp+4,5}, {8wp+6,7}

            asm("fma.rn.f32x2 %0, %1, %2, %3;" : "=l"(acc[ 0]) : "l"(d0), "l"(Wa.x), "l"(acc[ 0]));
            asm("fma.rn.f32x2 %0, %1, %2, %3;" : "=l"(acc[ 1]) : "l"(d0), "l"(Wa.y), "l"(acc[ 1]));
            asm("fma.rn.f32x2 %0, %1, %2, %3;" : "=l"(acc[ 2]) : "l"(d0), "l"(Wb.x), "l"(acc[ 2]));
            asm("fma.rn.f32x2 %0, %1, %2, %3;" : "=l"(acc[ 3]) : "l"(d0), "l"(Wb.y), "l"(acc[ 3]));
            asm("fma.rn.f32x2 %0, %1, %2, %3;" : "=l"(acc[ 4]) : "l"(d1), "l"(Wa.x), "l"(acc[ 4]));
            asm("fma.rn.f32x2 %0, %1, %2, %3;" : "=l"(acc[ 5]) : "l"(d1), "l"(Wa.y), "l"(acc[ 5]));
            asm("fma.rn.f32x2 %0, %1, %2, %3;" : "=l"(acc[ 6]) : "l"(d1), "l"(Wb.x), "l"(acc[ 6]));
            asm("fma.rn.f32x2 %0, %1, %2, %3;" : "=l"(acc[ 7]) : "l"(d1), "l"(Wb.y), "l"(acc[ 7]));
            asm("fma.rn.f32x2 %0, %1, %2, %3;" : "=l"(acc[ 8]) : "l"(d2), "l"(Wa.x), "l"(acc[ 8]));
            asm("fma.rn.f32x2 %0, %1, %2, %3;" : "=l"(acc[ 9]) : "l"(d2), "l"(Wa.y), "l"(acc[ 9]));
            asm("fma.rn.f32x2 %0, %1, %2, %3;" : "=l"(acc[10]) : "l"(d2), "l"(Wb.x), "l"(acc[10]));
            asm("fma.rn.f32x2 %0, %1, %2, %3;" : "=l"(acc[11]) : "l"(d2), "l"(Wb.y), "l"(acc[11]));
            asm("fma.rn.f32x2 %0, %1, %2, %3;" : "=l"(acc[12]) : "l"(d3), "l"(Wa.x), "l"(acc[12]));
            asm("fma.rn.f32x2 %0, %1, %2, %3;" : "=l"(acc[13]) : "l"(d3), "l"(Wa.y), "l"(acc[13]));
            asm("fma.rn.f32x2 %0, %1, %2, %3;" : "=l"(acc[14]) : "l"(d3), "l"(Wb.x), "l"(acc[14]));
            asm("fma.rn.f32x2 %0, %1, %2, %3;" : "=l"(acc[15]) : "l"(d3), "l"(Wb.y), "l"(acc[15]));
        }

        // ---- bounce this pass into its half of the blob ----
        // acc[r*4+j] = {out[4q+r][8wp+2j], out[4q+r][8wp+2j+1]}.
        // Chunk (r, jl) = w [8wp+4jl, +4) = {acc[r*4+2jl], acc[r*4+2jl+1]},
        // stored at slot ((r*2+jl) + q + off) & 7 in region half+pt*512+q*32.
        {
            const int half = (wp == 0) ? 1024 : 0;
            const int soff = (wp == 0) ? 0 : 4;
            float* sb = sou + half + pt * 512 + q * 32;
            #pragma unroll
            for (int i2 = 0; i2 < 8; i2++) {
                const int r  = i2 >> 1;
                const int jl = i2 & 1;
                const int s  = (i2 + q + soff) & 7;
                *(ulonglong2*)(sb + s * 4) =
                    make_ulonglong2(acc[r * 4 + 2 * jl], acc[r * 4 + 2 * jl + 1]);
            }
        }
    }
    __syncwarp();

    // ---- coalesced flush of both points (2048 floats) ----
    // flat = j*128 + lane*4. fpt=flat>>10; c=(flat&1023)>>4; w=flat&15;
    // qq=c>>2; r=c&3; jq=w>>2; jl=jq&1; half/off by jq<2 (pass 0 = upper).
    {
        float* o = out + (size_t)pair * 2048;
        #pragma unroll
        for (int j = 0; j < 16; j++) {
            const int flat = j * 128 + lane * 4;
            const int fpt  = flat >> 10;
            const int rem  = flat & 1023;
            const int c    = rem >> 4;
            const int w    = rem & 15;
            const int qq   = c >> 2;
            const int r    = c & 3;
            const int jq   = w >> 2;
            const int jl   = jq & 1;
            const int half = (jq < 2) ? 1024 : 0;
            const int soff = (jq < 2) ? 0 : 4;
            const int s    = (r * 2 + jl + qq + soff) & 7;
            const float4 v = *(const float4*)(sou + half + fpt * 512 + qq * 32 + s * 4);
            __stcs((float4*)(o + flat), v);
        }
    }
}

extern "C" void kernel_launch(void* const* d_in, const int* in_sizes, int n_in,
                              void* d_out, int out_size) {
    const float* feat = (const float*)d_in[0];
    const void*  inds = d_in[1];
    const float* guid = (const float*)d_in[2];
    const float* wn   = (const float*)d_in[3];
    float* out = (float*)d_out;

    detect_idx_kernel<<<1, 32>>>((const unsigned int*)inds);
    pcf_kernel<<<(B_ * M_) / 8, 128>>>(feat, inds, guid, wn, out);
}